// round 3
// baseline (speedup 1.0000x reference)
#include <cuda_runtime.h>
#include <math.h>

#define NANCH 49104
#define NCLS  90
#define NBATCH 8
#define NTASK (NBATCH * NCLS)   // 720
#define KPRE  5000
#define KPOST 100

// ---------------- scratch (device globals: no allocation allowed) ----------------
__device__ unsigned g_keysT[(size_t)NTASK * NANCH];      // transposed order-preserving keys
__device__ float4   g_cand_boxes[NTASK * KPRE];
__device__ float    g_cand_scores[NTASK * KPRE];
__device__ float4   g_nms_boxes[NTASK * KPOST];
__device__ float    g_nms_scores[NTASK * KPOST];

__constant__ int c_lvl_off[6]    = {0, 36864, 46080, 48384, 48960, 49104};
__constant__ int c_lvl_feat[5]   = {64, 32, 16, 8, 4};
__constant__ int c_lvl_stride[5] = {8, 16, 32, 64, 128};

__device__ __forceinline__ unsigned f2key(float f) {
    unsigned u = __float_as_uint(f);
    return (u & 0x80000000u) ? ~u : (u | 0x80000000u);
}
__device__ __forceinline__ float key2f(unsigned k) {
    unsigned u = (k & 0x80000000u) ? (k ^ 0x80000000u) : ~k;
    return __uint_as_float(u);
}

// ---------------- kernel 1: transpose logits -> keys [B,C,N] ----------------
__global__ void k_transpose(const float* __restrict__ logits) {
    __shared__ unsigned tile[32][33];
    int b  = blockIdx.z;
    int n0 = blockIdx.x * 32, c0 = blockIdx.y * 32;
    #pragma unroll
    for (int j = 0; j < 4; ++j) {
        int ty = threadIdx.y + j * 8;
        int n = n0 + ty, c = c0 + threadIdx.x;
        if (n < NANCH && c < NCLS)
            tile[ty][threadIdx.x] = f2key(logits[((size_t)b * NANCH + n) * NCLS + c]);
    }
    __syncthreads();
    #pragma unroll
    for (int j = 0; j < 4; ++j) {
        int ty = threadIdx.y + j * 8;
        int c = c0 + ty, n = n0 + threadIdx.x;
        if (n < NANCH && c < NCLS)
            g_keysT[((size_t)b * NCLS + c) * NANCH + n] = tile[threadIdx.x][ty];
    }
}

// ---------------- kernel 2: exact top-5000 select (radix) + FP32 decode ----------------
#define SEL_T 1024
extern __shared__ unsigned smA[];
__global__ void __launch_bounds__(SEL_T) k_select(const float4* __restrict__ deltas) {
    unsigned* keys = smA;                       // [NANCH]
    unsigned* hist = smA + NANCH;               // [2048]   (passes only)
    int*      cidx = (int*)(smA + NANCH);       // [KPRE]   (after passes; aliases hist)
    __shared__ unsigned warpTot[32], warpOff[32];
    __shared__ int bc_v, bc_k;
    __shared__ int cntG, cntT;
    __shared__ float s_hh[45], s_hw[45];        // anchor half-sizes LUT

    int tid  = threadIdx.x;
    int lane = tid & 31;
    int wrp  = tid >> 5;
    int task = blockIdx.x;
    int b    = task / NCLS;

    // anchor LUT: identical FP64 ops as reference, once per block
    if (tid < 45) {
        int l = tid / 9, a = tid - l * 9;
        int stride = c_lvl_stride[l];
        int iscale = a / 3, ri = a - iscale * 3;
        double rr   = (ri == 0) ? 1.0 : (ri == 1 ? 0.5 : 2.0);
        double base = exp2((double)iscale / 3.0) * (double)stride * 4.0;
        double sq   = sqrt(rr);
        s_hh[tid] = (float)(base / sq / 2.0);
        s_hw[tid] = (float)(base * sq / 2.0);
    }

    const unsigned* kt = g_keysT + (size_t)task * NANCH;
    for (int i = tid; i < NANCH; i += SEL_T) keys[i] = kt[i];
    __syncthreads();

    unsigned prefix = 0;
    int Krem = KPRE;
    const int SH[3] = {21, 10, 0};
    const int BT[3] = {11, 11, 10};

    for (int pass = 0; pass < 3; ++pass) {
        int shift = SH[pass], bits = BT[pass], nb = 1 << bits;
        for (int i = tid; i < nb; i += SEL_T) hist[i] = 0;
        __syncthreads();
        int top = shift + bits;
        // histogram with per-warp match aggregation (convergent full-warp loop)
        for (int base = 0; base < NANCH; base += SEL_T) {
            int i = base + tid;
            bool inb = i < NANCH;
            unsigned k = inb ? keys[i] : 0u;
            bool valid = inb && (pass == 0 || (k >> top) == prefix);
            unsigned bin = (k >> shift) & (unsigned)(nb - 1);
            unsigned tag = valid ? bin : 0xffffffffu;
            unsigned m = __match_any_sync(0xffffffffu, tag);
            if (valid && (__ffs(m) - 1) == lane)
                atomicAdd(&hist[bin], (unsigned)__popc(m));
        }
        __syncthreads();
        // per-thread chunk sums, then shfl-based inclusive suffix scan
        int cs = nb >> 10;                 // bins per thread (2 or 1)
        int base0 = tid * cs;
        unsigned ssum = 0;
        for (int j2 = 0; j2 < cs; ++j2) ssum += hist[base0 + j2];
        unsigned s = ssum;
        #pragma unroll
        for (int o = 1; o < 32; o <<= 1) {
            unsigned t = __shfl_down_sync(0xffffffffu, s, o);
            if (lane + o < 32) s += t;
        }
        if (lane == 0) warpTot[wrp] = s;
        __syncthreads();
        if (tid < 32) {
            unsigned v = warpTot[tid];
            unsigned sv = v;
            #pragma unroll
            for (int o = 1; o < 32; o <<= 1) {
                unsigned t = __shfl_down_sync(0xffffffffu, sv, o);
                if (tid + o < 32) sv += t;
            }
            warpOff[tid] = sv - v;   // sum of totals of warps strictly after
        }
        __syncthreads();
        unsigned St = s + warpOff[wrp];     // inclusive suffix over thread chunks
        if (St >= (unsigned)Krem && (St - ssum) < (unsigned)Krem) {
            unsigned acc = St - ssum;
            for (int j2 = cs - 1; j2 >= 0; --j2) {
                unsigned hv = hist[base0 + j2];
                acc += hv;
                if (acc >= (unsigned)Krem) {
                    bc_v = base0 + j2;
                    bc_k = Krem - (int)(acc - hv);
                    break;
                }
            }
        }
        __syncthreads();
        prefix = (prefix << bits) | (unsigned)bc_v;
        Krem   = bc_k;
        __syncthreads();
    }
    unsigned Tkey = prefix;            // exact 5000th-largest key
    int needT = Krem;                  // ties of Tkey to include

    // ---- compact candidate indices (ballot-aggregated atomics) ----
    if (tid == 0) { cntG = 0; cntT = 0; }
    __syncthreads();
    for (int base = 0; base < NANCH; base += SEL_T) {
        int i = base + tid;
        bool pred = (i < NANCH) && (keys[i] > Tkey);
        unsigned mask = __ballot_sync(0xffffffffu, pred);
        if (pred) {
            int leader = __ffs(mask) - 1;
            int bslot = 0;
            if (lane == leader) bslot = atomicAdd(&cntG, __popc(mask));
            bslot = __shfl_sync(mask, bslot, leader);
            cidx[bslot + __popc(mask & ((1u << lane) - 1u))] = i;
        }
    }
    __syncthreads();
    int G = cntG;
    for (int i = tid; i < NANCH; i += SEL_T) {
        if (keys[i] == Tkey) {
            int t = atomicAdd(&cntT, 1);
            if (t < needT) cidx[G + t] = i;
        }
    }
    __syncthreads();

    // ---- dense FP32 decode: all lanes active ----
    for (int sidx = tid; sidx < KPRE; sidx += SEL_T) {
        int n = cidx[sidx];
        unsigned key = keys[n];

        int l = 0;
        #pragma unroll
        for (int q = 1; q < 5; ++q) if (n >= c_lvl_off[q]) l = q;
        int j    = n - c_lvl_off[l];
        int cell = j / 9, a = j - cell * 9;
        int feat = c_lvl_feat[l];
        int row  = cell / feat, col = cell - row * feat;
        int stride = c_lvl_stride[l];

        float hh = s_hh[l * 9 + a];
        float hw = s_hw[l * 9 + a];

        float cy = ((float)row + 0.5f) * (float)stride;
        float cx = ((float)col + 0.5f) * (float)stride;
        float ay1 = __fsub_rn(cy, hh), ay2 = __fadd_rn(cy, hh);
        float ax1 = __fsub_rn(cx, hw), ax2 = __fadd_rn(cx, hw);
        float ah  = __fsub_rn(ay2, ay1), aw = __fsub_rn(ax2, ax1);
        float acy = __fmul_rn(__fadd_rn(ay1, ay2), 0.5f);
        float acx = __fmul_rn(__fadd_rn(ax1, ax2), 0.5f);

        float4 d = deltas[(size_t)b * NANCH + n];
        float ncy = __fadd_rn(__fmul_rn(d.x, ah), acy);
        float ncx = __fadd_rn(__fmul_rn(d.y, aw), acx);
        float h   = __fmul_rn(expf(d.z), ah);
        float w   = __fmul_rn(expf(d.w), aw);

        const float inv = 1.0f / 512.0f;
        float y1 = __fsub_rn(ncy, __fmul_rn(h, 0.5f)) * inv;
        float x1 = __fsub_rn(ncx, __fmul_rn(w, 0.5f)) * inv;
        float y2 = __fadd_rn(ncy, __fmul_rn(h, 0.5f)) * inv;
        float x2 = __fadd_rn(ncx, __fmul_rn(w, 0.5f)) * inv;
        y1 = fminf(fmaxf(y1, 0.0f), 1.0f);
        x1 = fminf(fmaxf(x1, 0.0f), 1.0f);
        y2 = fminf(fmaxf(y2, 0.0f), 1.0f);
        x2 = fminf(fmaxf(x2, 0.0f), 1.0f);

        float logit = key2f(key);
        float sc = __fdiv_rn(1.0f, __fadd_rn(1.0f, expf(-logit)));
        g_cand_scores[(size_t)task * KPRE + sidx] = sc;
        g_cand_boxes [(size_t)task * KPRE + sidx] = make_float4(y1, x1, y2, x2);
    }
}

// ---------------- kernel 3: greedy NMS (100 picks) per task ----------------
#define NMS_T 1024
extern __shared__ unsigned char smB[];
__global__ void __launch_bounds__(NMS_T) k_nms() {
    float4* bx = (float4*)smB;                 // [KPRE]
    float*  s  = (float*)(smB + KPRE * 16);    // [KPRE]
    __shared__ unsigned long long g_red;

    int tid = threadIdx.x, task = blockIdx.x;
    int lane = tid & 31;
    const float*  cs = g_cand_scores + (size_t)task * KPRE;
    const float4* cb = g_cand_boxes  + (size_t)task * KPRE;
    for (int i = tid; i < KPRE; i += NMS_T) { s[i] = cs[i]; bx[i] = cb[i]; }
    if (tid == 0) g_red = 0ull;
    __syncthreads();

    for (int p = 0; p < KPOST; ++p) {
        // ---- stable argmax: local scan -> warp reduce -> leader atomicMax ----
        float v = -1e30f; int idx = 0;
        for (int i = tid; i < KPRE; i += NMS_T) {
            float sv = s[i];
            if (sv > v) { v = sv; idx = i; }
        }
        #pragma unroll
        for (int o = 16; o; o >>= 1) {
            float ov = __shfl_down_sync(0xffffffffu, v, o);
            int   oi = __shfl_down_sync(0xffffffffu, idx, o);
            if (ov > v || (ov == v && oi < idx)) { v = ov; idx = oi; }
        }
        if (lane == 0) {
            unsigned long long pk =
                ((unsigned long long)f2key(v) << 32) | (unsigned)(0xffffffffu - (unsigned)idx);
            atomicMax(&g_red, pk);
        }
        __syncthreads();
        unsigned long long r = g_red;
        float rv = key2f((unsigned)(r >> 32));
        int   ri = (int)(0xffffffffu - (unsigned)(r & 0xffffffffu));

        if (rv <= 0.2f) {   // all remaining picks invalid -> zeros
            for (int q = p + tid; q < KPOST; q += NMS_T) {
                g_nms_scores[(size_t)task * KPOST + q] = 0.0f;
                g_nms_boxes [(size_t)task * KPOST + q] = make_float4(0.f, 0.f, 0.f, 0.f);
            }
            break;
        }
        float4 bb = bx[ri];
        if (tid == 0) {
            g_nms_scores[(size_t)task * KPOST + p] = rv;
            g_nms_boxes [(size_t)task * KPOST + p] = bb;
        }
        // ---- suppression ----
        float a1 = __fmul_rn(__fsub_rn(bb.z, bb.x), __fsub_rn(bb.w, bb.y));
        for (int i = tid; i < KPRE; i += NMS_T) {
            float4 o4 = bx[i];
            float yy1 = fmaxf(bb.x, o4.x), xx1 = fmaxf(bb.y, o4.y);
            float yy2 = fminf(bb.z, o4.z), xx2 = fminf(bb.w, o4.w);
            float ih = fmaxf(__fsub_rn(yy2, yy1), 0.0f);
            float iw = fmaxf(__fsub_rn(xx2, xx1), 0.0f);
            float inter = __fmul_rn(ih, iw);
            float a2 = __fmul_rn(__fsub_rn(o4.z, o4.x), __fsub_rn(o4.w, o4.y));
            float den = __fadd_rn(__fsub_rn(__fadd_rn(a1, a2), inter), 1e-8f);
            float iou = __fdiv_rn(inter, den);
            if (iou > 0.5f) s[i] = -1.0f;
        }
        if (tid == 0) g_red = 0ull;
        __syncthreads();
    }
}

// ---------------- kernel 4: 90-way sorted-list merge top-100 per batch ----------------
__global__ void __launch_bounds__(128) k_final(float* __restrict__ out) {
    __shared__ float sc[NCLS * KPOST];   // 9000 floats
    __shared__ int   pickFlat[KPOST];
    __shared__ float pickVal[KPOST];

    int b = blockIdx.x, tid = threadIdx.x;
    const float* src = g_nms_scores + (size_t)b * NCLS * KPOST;
    for (int i = tid; i < NCLS * KPOST; i += 128) sc[i] = src[i];
    __syncthreads();

    if (tid < 32) {
        int lane = tid;
        int head0 = 0, head1 = 0, head2 = 0;   // classes lane, lane+32, lane+64
        for (int p = 0; p < KPOST; ++p) {
            unsigned long long best = 0ull;
            // candidate from each owned class head (lists are descending)
            {
                int c = lane;            // always < 90
                if (head0 < KPOST) {
                    int flat = c * KPOST + head0;
                    best = ((unsigned long long)f2key(sc[flat]) << 32) | (unsigned)(~flat);
                }
            }
            {
                int c = lane + 32;       // always < 90
                if (head1 < KPOST) {
                    int flat = c * KPOST + head1;
                    unsigned long long pk =
                        ((unsigned long long)f2key(sc[flat]) << 32) | (unsigned)(~flat);
                    if (pk > best) best = pk;
                }
            }
            if (lane + 64 < NCLS) {
                int c = lane + 64;
                if (head2 < KPOST) {
                    int flat = c * KPOST + head2;
                    unsigned long long pk =
                        ((unsigned long long)f2key(sc[flat]) << 32) | (unsigned)(~flat);
                    if (pk > best) best = pk;
                }
            }
            // butterfly max: all lanes get the global best
            #pragma unroll
            for (int o = 16; o; o >>= 1) {
                unsigned long long ob = __shfl_xor_sync(0xffffffffu, best, o);
                if (ob > best) best = ob;
            }
            int flat = (int)(~(unsigned)(best & 0xffffffffu));
            float sv = key2f((unsigned)(best >> 32));
            int cls = flat / KPOST;
            if (lane == (cls & 31)) {      // owner advances its head
                int t = cls >> 5;
                if (t == 0) head0++; else if (t == 1) head1++; else head2++;
            }
            if (lane == 0) { pickFlat[p] = flat; pickVal[p] = sv; }
        }
    }
    __syncthreads();

    // parallel output assembly
    for (int p = tid; p < KPOST; p += 128) {
        int flat = pickFlat[p]; float rv = pickVal[p];
        float4 bb = g_nms_boxes[(size_t)b * NCLS * KPOST + flat];
        float* ob = out + ((size_t)b * KPOST + p) * 4;
        ob[0] = bb.x; ob[1] = bb.y; ob[2] = bb.z; ob[3] = bb.w;
        out[NBATCH * KPOST * 4 + b * KPOST + p] = rv;
        out[NBATCH * KPOST * 5 + b * KPOST + p] = (float)(flat / KPOST);
    }
    if (tid == 0) {
        int validc = 0;
        for (int p = 0; p < KPOST; ++p) if (pickVal[p] > 0.0f) validc++;
        out[NBATCH * KPOST * 6 + b] = (float)validc;
    }
}

// ---------------- launch ----------------
extern "C" void kernel_launch(void* const* d_in, const int* in_sizes, int n_in,
                              void* d_out, int out_size) {
    const float* a0 = (const float*)d_in[0];
    const float* a1 = (const float*)d_in[1];
    const float4* deltas;
    const float*  logits;
    if (in_sizes[0] == NBATCH * NANCH * 4) { deltas = (const float4*)a0; logits = a1; }
    else                                   { deltas = (const float4*)a1; logits = a0; }
    float* out = (float*)d_out;

    cudaFuncSetAttribute(k_select, cudaFuncAttributeMaxDynamicSharedMemorySize,
                         (NANCH + KPRE) * 4);
    cudaFuncSetAttribute(k_nms, cudaFuncAttributeMaxDynamicSharedMemorySize,
                         KPRE * 20);

    dim3 gT((NANCH + 31) / 32, (NCLS + 31) / 32, NBATCH);
    k_transpose<<<gT, dim3(32, 8)>>>(logits);
    k_select<<<NTASK, SEL_T, (NANCH + KPRE) * 4>>>(deltas);
    k_nms<<<NTASK, NMS_T, KPRE * 20>>>();
    k_final<<<NBATCH, 128>>>(out);
}

// round 4
// speedup vs baseline: 1.5549x; 1.5549x over previous
#include <cuda_runtime.h>
#include <math.h>

#define NANCH 49104
#define NCLS  90
#define NBATCH 8
#define NTASK (NBATCH * NCLS)   // 720
#define KPRE  5000
#define KPOST 100
#define SEL_T 512
#define NMS_T 512
#define FIN_T 512
#define SEG   96                // ceil(NANCH / SEL_T)

typedef unsigned long long u64;

// ---------------- scratch (device globals: no allocation allowed) ----------------
__device__ unsigned g_keysT[(size_t)NTASK * NANCH];
__device__ float4   g_cand_boxes[NTASK * KPRE];
__device__ float    g_cand_scores[NTASK * KPRE];
__device__ float4   g_nms_boxes[NTASK * KPOST];
__device__ float    g_nms_scores[NTASK * KPOST];

__constant__ int c_lvl_off[6]    = {0, 36864, 46080, 48384, 48960, 49104};
__constant__ int c_lvl_feat[5]   = {64, 32, 16, 8, 4};
__constant__ int c_lvl_stride[5] = {8, 16, 32, 64, 128};

__device__ __forceinline__ unsigned f2key(float f) {
    unsigned u = __float_as_uint(f);
    return (u & 0x80000000u) ? ~u : (u | 0x80000000u);
}
__device__ __forceinline__ float key2f(unsigned k) {
    unsigned u = (k & 0x80000000u) ? (k ^ 0x80000000u) : ~k;
    return __uint_as_float(u);
}

// IoU > 0.5, bit-identical op sequence to the reference
__device__ __forceinline__ bool iou_gt(const float4 a, const float4 b) {
    float yy1 = fmaxf(a.x, b.x), xx1 = fmaxf(a.y, b.y);
    float yy2 = fminf(a.z, b.z), xx2 = fminf(a.w, b.w);
    float ih = fmaxf(__fsub_rn(yy2, yy1), 0.0f);
    float iw = fmaxf(__fsub_rn(xx2, xx1), 0.0f);
    float inter = __fmul_rn(ih, iw);
    float a1 = __fmul_rn(__fsub_rn(a.z, a.x), __fsub_rn(a.w, a.y));
    float a2 = __fmul_rn(__fsub_rn(b.z, b.x), __fsub_rn(b.w, b.y));
    float den = __fadd_rn(__fsub_rn(__fadd_rn(a1, a2), inter), 1e-8f);
    return __fdiv_rn(inter, den) > 0.5f;
}

// inclusive SUFFIX scan over 512 per-thread values; returns this-thread-and-later sum
__device__ __forceinline__ unsigned sufscan512(unsigned ssum, unsigned* wA, unsigned* wB) {
    int lane = threadIdx.x & 31, wrp = threadIdx.x >> 5;
    unsigned s = ssum;
    #pragma unroll
    for (int o = 1; o < 32; o <<= 1) {
        unsigned t = __shfl_down_sync(0xffffffffu, s, o);
        if (lane + o < 32) s += t;
    }
    if (lane == 0) wA[wrp] = s;
    __syncthreads();
    if (threadIdx.x < 32) {
        unsigned v = (threadIdx.x < 16) ? wA[threadIdx.x] : 0u;
        unsigned sv = v;
        #pragma unroll
        for (int o = 1; o < 32; o <<= 1) {
            unsigned t = __shfl_down_sync(0xffffffffu, sv, o);
            if (threadIdx.x + o < 32) sv += t;
        }
        if (threadIdx.x < 16) wB[threadIdx.x] = sv - v;
    }
    __syncthreads();
    return s + wB[wrp];
}

// ---------------- kernel 1: transpose logits -> keys [B,C,N] ----------------
__global__ void k_transpose(const float* __restrict__ logits) {
    __shared__ unsigned tile[32][33];
    int b  = blockIdx.z;
    int n0 = blockIdx.x * 32, c0 = blockIdx.y * 32;
    #pragma unroll
    for (int j = 0; j < 4; ++j) {
        int ty = threadIdx.y + j * 8;
        int n = n0 + ty, c = c0 + threadIdx.x;
        if (n < NANCH && c < NCLS)
            tile[ty][threadIdx.x] = f2key(logits[((size_t)b * NANCH + n) * NCLS + c]);
    }
    __syncthreads();
    #pragma unroll
    for (int j = 0; j < 4; ++j) {
        int ty = threadIdx.y + j * 8;
        int c = c0 + ty, n = n0 + threadIdx.x;
        if (n < NANCH && c < NCLS)
            g_keysT[((size_t)b * NCLS + c) * NANCH + n] = tile[threadIdx.x][ty];
    }
}

// ---------------- kernel 2: exact top-5000 select + stable compaction + decode ----------------
extern __shared__ unsigned smA[];
__global__ void __launch_bounds__(SEL_T) k_select(const float4* __restrict__ deltas) {
    unsigned* keys = smA;                       // [NANCH]
    unsigned* hist = smA + NANCH;               // [2048]  (aliased by cidx after passes)
    int*      cidx = (int*)(smA + NANCH);       // [KPRE]
    __shared__ unsigned wA[16], wB[16];
    __shared__ int s_bcv, s_bck;
    __shared__ unsigned s_grand;
    __shared__ float s_hh[45], s_hw[45];

    int tid  = threadIdx.x;
    int lane = tid & 31, wrp = tid >> 5;
    int task = blockIdx.x;
    int b    = task / NCLS;

    // anchor LUT: identical FP64 ops as reference, once per block
    if (tid < 45) {
        int l = tid / 9, a = tid - l * 9;
        int stride = c_lvl_stride[l];
        int iscale = a / 3, ri = a - iscale * 3;
        double rr   = (ri == 0) ? 1.0 : (ri == 1 ? 0.5 : 2.0);
        double base = exp2((double)iscale / 3.0) * (double)stride * 4.0;
        double sq   = sqrt(rr);
        s_hh[tid] = (float)(base / sq / 2.0);
        s_hw[tid] = (float)(base * sq / 2.0);
    }

    const unsigned* kt = g_keysT + (size_t)task * NANCH;
    #pragma unroll 4
    for (int i = tid; i < NANCH; i += SEL_T) keys[i] = kt[i];
    __syncthreads();

    unsigned prefix = 0;
    int Krem = KPRE;
    const int SH[3] = {21, 10, 0};
    const int BT[3] = {11, 11, 10};

    for (int pass = 0; pass < 3; ++pass) {
        int shift = SH[pass], bits = BT[pass], nb = 1 << bits, top = shift + bits;
        for (int i = tid; i < nb; i += SEL_T) hist[i] = 0;
        __syncthreads();
        for (int base = 0; base < NANCH; base += SEL_T) {
            int i = base + tid;
            bool inb = i < NANCH;
            unsigned k = inb ? keys[i] : 0u;
            bool valid = inb && (pass == 0 || (k >> top) == prefix);
            unsigned bin = (k >> shift) & (unsigned)(nb - 1);
            unsigned tag = valid ? bin : 0xffffffffu;
            unsigned m = __match_any_sync(0xffffffffu, tag);
            if (valid && (__ffs(m) - 1) == lane)
                atomicAdd(&hist[bin], (unsigned)__popc(m));
        }
        __syncthreads();
        int cs = nb >> 9;                 // 4,4,2
        int base0 = tid * cs;
        unsigned ssum = 0;
        for (int j = 0; j < cs; ++j) ssum += hist[base0 + j];
        unsigned St = sufscan512(ssum, wA, wB);
        if (St >= (unsigned)Krem && (St - ssum) < (unsigned)Krem) {
            unsigned acc = St - ssum;
            for (int j = cs - 1; j >= 0; --j) {
                unsigned hv = hist[base0 + j];
                acc += hv;
                if (acc >= (unsigned)Krem) {
                    s_bcv = base0 + j;
                    s_bck = Krem - (int)(acc - hv);
                    break;
                }
            }
        }
        __syncthreads();
        prefix = (prefix << bits) | (unsigned)s_bcv;
        Krem   = s_bck;
        __syncthreads();
    }
    unsigned Tkey = prefix;
    int needT = Krem;

    // ---- STABLE compaction: per-thread contiguous segments + block scan ----
    int segB = tid * SEG;
    int segE = min(segB + SEG, NANCH);
    int cg = 0, ct = 0;
    #pragma unroll 4
    for (int i = segB; i < segE; ++i) {
        unsigned k = keys[i];
        cg += (k > Tkey); ct += (k == Tkey);
    }
    unsigned packed = ((unsigned)cg << 16) | (unsigned)ct;
    unsigned s = packed;
    #pragma unroll
    for (int o = 1; o < 32; o <<= 1) {
        unsigned t = __shfl_up_sync(0xffffffffu, s, o);
        if (lane >= o) s += t;
    }
    if (lane == 31) wA[wrp] = s;
    __syncthreads();
    if (tid < 32) {
        unsigned v = (tid < 16) ? wA[tid] : 0u;
        unsigned sv = v;
        #pragma unroll
        for (int o = 1; o < 32; o <<= 1) {
            unsigned t = __shfl_up_sync(0xffffffffu, sv, o);
            if (tid >= o) sv += t;
        }
        if (tid < 16) wB[tid] = sv - v;
        if (tid == 15) s_grand = sv;
    }
    __syncthreads();
    unsigned excl = wB[wrp] + (s - packed);
    int offG = excl >> 16, offT = excl & 0xffffu;
    int G = (int)(s_grand >> 16);        // == KPRE - needT

    int gG = offG, gT = offT;
    for (int i = segB; i < segE; ++i) {
        unsigned k = keys[i];
        if (k > Tkey)       cidx[gG++] = i;
        else if (k == Tkey) { if (gT < needT) cidx[G + gT] = i; gT++; }
    }
    __syncthreads();

    // ---- dense FP32 decode ----
    for (int sidx = tid; sidx < KPRE; sidx += SEL_T) {
        int n = cidx[sidx];
        unsigned key = keys[n];

        int l = 0;
        #pragma unroll
        for (int q = 1; q < 5; ++q) if (n >= c_lvl_off[q]) l = q;
        int j    = n - c_lvl_off[l];
        int cell = j / 9, a = j - cell * 9;
        int feat = c_lvl_feat[l];
        int row  = cell / feat, col = cell - row * feat;
        int stride = c_lvl_stride[l];

        float hh = s_hh[l * 9 + a];
        float hw = s_hw[l * 9 + a];

        float cy = ((float)row + 0.5f) * (float)stride;
        float cx = ((float)col + 0.5f) * (float)stride;
        float ay1 = __fsub_rn(cy, hh), ay2 = __fadd_rn(cy, hh);
        float ax1 = __fsub_rn(cx, hw), ax2 = __fadd_rn(cx, hw);
        float ah  = __fsub_rn(ay2, ay1), aw = __fsub_rn(ax2, ax1);
        float acy = __fmul_rn(__fadd_rn(ay1, ay2), 0.5f);
        float acx = __fmul_rn(__fadd_rn(ax1, ax2), 0.5f);

        float4 d = deltas[(size_t)b * NANCH + n];
        float ncy = __fadd_rn(__fmul_rn(d.x, ah), acy);
        float ncx = __fadd_rn(__fmul_rn(d.y, aw), acx);
        float h   = __fmul_rn(expf(d.z), ah);
        float w   = __fmul_rn(expf(d.w), aw);

        const float inv = 1.0f / 512.0f;
        float y1 = __fsub_rn(ncy, __fmul_rn(h, 0.5f)) * inv;
        float x1 = __fsub_rn(ncx, __fmul_rn(w, 0.5f)) * inv;
        float y2 = __fadd_rn(ncy, __fmul_rn(h, 0.5f)) * inv;
        float x2 = __fadd_rn(ncx, __fmul_rn(w, 0.5f)) * inv;
        y1 = fminf(fmaxf(y1, 0.0f), 1.0f);
        x1 = fminf(fmaxf(x1, 0.0f), 1.0f);
        y2 = fminf(fmaxf(y2, 0.0f), 1.0f);
        x2 = fminf(fmaxf(x2, 0.0f), 1.0f);

        float logit = key2f(key);
        float sc = __fdiv_rn(1.0f, __fadd_rn(1.0f, expf(-logit)));
        g_cand_scores[(size_t)task * KPRE + sidx] = sc;
        g_cand_boxes [(size_t)task * KPRE + sidx] = make_float4(y1, x1, y2, x2);
    }
}

// ---------------- kernel 3: sorted sequential-scan NMS ----------------
// batches of 1024: radix-select -> bitonic sort -> warp0 serial scan
extern __shared__ unsigned char smB[];
__global__ void __launch_bounds__(NMS_T) k_nms() {
    float4*   bxs  = (float4*)smB;                    // [KPRE]   80000 B
    u64*      ck   = (u64*)(smB + 80000);             // [KPRE]   40000 B
    u64*      sb   = (u64*)(smB + 120000);            // [1024]    8192 B
    unsigned* hist = (unsigned*)(smB + 128192);       // [4096]   16384 B
    __shared__ float4 s_abox[KPOST];
    __shared__ unsigned wA[16], wB[16];
    __shared__ int s_bcv, s_bck, s_cnt, s_na, s_done;

    int tid = threadIdx.x, task = blockIdx.x;
    const float*  cs = g_cand_scores + (size_t)task * KPRE;
    const float4* cb = g_cand_boxes  + (size_t)task * KPRE;
    #pragma unroll 2
    for (int i = tid; i < KPRE; i += NMS_T) {
        float sc = cs[i];
        bxs[i] = cb[i];
        ck[i] = ((u64)f2key(sc) << 13) | (u64)(8191 - i);   // slot asc = tie order
    }
    if (tid == 0) { s_na = 0; s_done = 0; }
    __syncthreads();

    u64 Tprev = ~0ull;
    for (int bstart = 0; bstart < KPRE; bstart += 1024) {
        int rem = KPRE - bstart;
        u64 Tb = 0;
        if (rem > 1024) {
            // 4-pass radix select: top-1024 of keys < Tprev (45-bit keys, unique)
            u64 pref = 0; int Krem = 1024;
            const int SHs[4] = {33, 21, 9, 0};
            const int BTs[4] = {12, 12, 12, 9};
            for (int p = 0; p < 4; ++p) {
                int shift = SHs[p], bits = BTs[p], nb = 1 << bits, top = shift + bits;
                for (int i = tid; i < nb; i += NMS_T) hist[i] = 0;
                __syncthreads();
                for (int i = tid; i < KPRE; i += NMS_T) {
                    u64 k = ck[i];
                    if (k < Tprev && (k >> top) == pref)
                        atomicAdd(&hist[(unsigned)((k >> shift) & (u64)(nb - 1))], 1u);
                }
                __syncthreads();
                int csz = nb >> 9; if (csz == 0) csz = 1;
                int base0 = tid * csz;
                unsigned ssum = 0;
                for (int j = 0; j < csz; ++j) ssum += hist[base0 + j];
                unsigned St = sufscan512(ssum, wA, wB);
                if (St >= (unsigned)Krem && (St - ssum) < (unsigned)Krem) {
                    unsigned acc = St - ssum;
                    for (int j = csz - 1; j >= 0; --j) {
                        unsigned hv = hist[base0 + j];
                        acc += hv;
                        if (acc >= (unsigned)Krem) {
                            s_bcv = base0 + j;
                            s_bck = Krem - (int)(acc - hv);
                            break;
                        }
                    }
                }
                __syncthreads();
                pref = (pref << bits) | (u64)(unsigned)s_bcv;
                Krem = s_bck;
                __syncthreads();
            }
            Tb = pref;
        }
        // compact batch (order-free: bitonic fully sorts, keys unique)
        if (tid == 0) s_cnt = 0;
        for (int i = tid; i < 1024; i += NMS_T) sb[i] = 0;
        __syncthreads();
        for (int i = tid; i < KPRE; i += NMS_T) {
            u64 k = ck[i];
            if (k >= Tb && k < Tprev) sb[atomicAdd(&s_cnt, 1)] = k;
        }
        __syncthreads();
        Tprev = Tb;

        // bitonic sort sb[1024] DESCENDING (512 pairs, 1 per thread per round)
        for (int k2 = 2; k2 <= 1024; k2 <<= 1) {
            for (int j = k2 >> 1; j > 0; j >>= 1) {
                int p = tid;
                int i = ((p & ~(j - 1)) << 1) | (p & (j - 1));
                int ix = i | j;
                u64 a = sb[i], b2 = sb[ix];
                bool asc = ((i & k2) == 0);
                if ((a < b2) == asc) { sb[i] = b2; sb[ix] = a; }
                __syncthreads();
            }
        }

        // warp 0: serial greedy scan, warp-parallel tests vs accepted list
        if (tid < 32) {
            int lane = tid;
            int cnt = s_na;
            int dn  = s_done;
            if (!dn) {
                for (int f = 0; f < 1024 && cnt < KPOST; ++f) {
                    u64 key = sb[f];
                    if (key == 0ull) break;                    // padding: batch exhausted
                    float sc = key2f((unsigned)(key >> 13));
                    if (!(sc > 0.2f)) { dn = 1; break; }       // all later invalid
                    int slot = 8191 - (int)(key & 8191ull);
                    float4 cb4 = bxs[slot];
                    bool sup = false;
                    for (int a = lane; a < cnt; a += 32) {
                        if (iou_gt(s_abox[a], cb4)) { sup = true; break; }
                    }
                    if (!__any_sync(0xffffffffu, sup)) {
                        if (lane == 0) {
                            g_nms_scores[(size_t)task * KPOST + cnt] = sc;
                            g_nms_boxes [(size_t)task * KPOST + cnt] = cb4;
                            s_abox[cnt] = cb4;
                        }
                        __syncwarp();
                        cnt++;
                    }
                }
            }
            if (lane == 0) { s_na = cnt; s_done = dn; }
        }
        __syncthreads();
        if (s_na >= KPOST || s_done) break;
    }
    // zero-fill tail
    for (int q = s_na + tid; q < KPOST; q += NMS_T) {
        g_nms_scores[(size_t)task * KPOST + q] = 0.0f;
        g_nms_boxes [(size_t)task * KPOST + q] = make_float4(0.f, 0.f, 0.f, 0.f);
    }
}

// ---------------- kernel 4: per-batch top-100 of 9000 (radix select + rank) ----------------
extern __shared__ u64 smF[];
__global__ void __launch_bounds__(FIN_T) k_final(float* __restrict__ out) {
    u64*      ck   = smF;                          // [9000]
    unsigned* hist = (unsigned*)(smF + NCLS * KPOST); // [4096]
    __shared__ unsigned wA[16], wB[16];
    __shared__ int s_bcv, s_bck, s_cnt, s_valid;
    __shared__ u64 surv[KPOST];

    int b = blockIdx.x, tid = threadIdx.x;
    const float* src = g_nms_scores + (size_t)b * NCLS * KPOST;
    for (int i = tid; i < NCLS * KPOST; i += FIN_T)
        ck[i] = ((u64)f2key(src[i]) << 14) | (u64)(16383 - i);  // flat asc = tie order
    if (tid == 0) { s_cnt = 0; s_valid = 0; }
    __syncthreads();

    u64 pref = 0; int Krem = KPOST;
    const int SHs[4] = {34, 22, 10, 0};
    const int BTs[4] = {12, 12, 12, 10};
    for (int p = 0; p < 4; ++p) {
        int shift = SHs[p], bits = BTs[p], nb = 1 << bits, top = shift + bits;
        for (int i = tid; i < nb; i += FIN_T) hist[i] = 0;
        __syncthreads();
        for (int i = tid; i < NCLS * KPOST; i += FIN_T) {
            u64 k = ck[i];
            if ((k >> top) == pref)
                atomicAdd(&hist[(unsigned)((k >> shift) & (u64)(nb - 1))], 1u);
        }
        __syncthreads();
        int csz = nb >> 9; if (csz == 0) csz = 1;
        int base0 = tid * csz;
        unsigned ssum = 0;
        for (int j = 0; j < csz; ++j) ssum += hist[base0 + j];
        unsigned St = sufscan512(ssum, wA, wB);
        if (St >= (unsigned)Krem && (St - ssum) < (unsigned)Krem) {
            unsigned acc = St - ssum;
            for (int j = csz - 1; j >= 0; --j) {
                unsigned hv = hist[base0 + j];
                acc += hv;
                if (acc >= (unsigned)Krem) {
                    s_bcv = base0 + j;
                    s_bck = Krem - (int)(acc - hv);
                    break;
                }
            }
        }
        __syncthreads();
        pref = (pref << bits) | (u64)(unsigned)s_bcv;
        Krem = s_bck;
        __syncthreads();
    }
    u64 T = pref;   // keys unique -> exactly 100 keys >= T

    for (int i = tid; i < NCLS * KPOST; i += FIN_T) {
        u64 k = ck[i];
        if (k >= T) {
            int slot = atomicAdd(&s_cnt, 1);
            if (slot < KPOST) surv[slot] = k;
        }
    }
    __syncthreads();

    if (tid < KPOST) {
        u64 k = surv[tid];
        int rank = 0;
        #pragma unroll 4
        for (int j = 0; j < KPOST; ++j) rank += (surv[j] > k);
        int flat = 16383 - (int)(k & 16383ull);
        float sc = key2f((unsigned)(k >> 14));
        float4 bb = g_nms_boxes[(size_t)b * NCLS * KPOST + flat];
        float* ob = out + ((size_t)b * KPOST + rank) * 4;
        ob[0] = bb.x; ob[1] = bb.y; ob[2] = bb.z; ob[3] = bb.w;
        out[NBATCH * KPOST * 4 + b * KPOST + rank] = sc;
        out[NBATCH * KPOST * 5 + b * KPOST + rank] = (float)(flat / KPOST);
        if (sc > 0.0f) atomicAdd(&s_valid, 1);
    }
    __syncthreads();
    if (tid == 0) out[NBATCH * KPOST * 6 + b] = (float)s_valid;
}

// ---------------- launch ----------------
extern "C" void kernel_launch(void* const* d_in, const int* in_sizes, int n_in,
                              void* d_out, int out_size) {
    const float* a0 = (const float*)d_in[0];
    const float* a1 = (const float*)d_in[1];
    const float4* deltas;
    const float*  logits;
    if (in_sizes[0] == NBATCH * NANCH * 4) { deltas = (const float4*)a0; logits = a1; }
    else                                   { deltas = (const float4*)a1; logits = a0; }
    float* out = (float*)d_out;

    const int selSm = (NANCH + KPRE) * 4;          // 216,416
    const int nmsSm = 80000 + 40000 + 8192 + 16384; // 144,576
    const int finSm = NCLS * KPOST * 8 + 4096 * 4;  //  88,384

    cudaFuncSetAttribute(k_select, cudaFuncAttributeMaxDynamicSharedMemorySize, selSm);
    cudaFuncSetAttribute(k_nms,    cudaFuncAttributeMaxDynamicSharedMemorySize, nmsSm);
    cudaFuncSetAttribute(k_final,  cudaFuncAttributeMaxDynamicSharedMemorySize, finSm);

    dim3 gT((NANCH + 31) / 32, (NCLS + 31) / 32, NBATCH);
    k_transpose<<<gT, dim3(32, 8)>>>(logits);
    k_select<<<NTASK, SEL_T, selSm>>>(deltas);
    k_nms<<<NTASK, NMS_T, nmsSm>>>();
    k_final<<<NBATCH, FIN_T, finSm>>>(out);
}